// round 15
// baseline (speedup 1.0000x reference)
#include <cuda_runtime.h>
#include <cuda_bf16.h>
#include <stdint.h>
#include <math.h>

// Problem constants
#define BATCH 8192
#define DIM   512
#define HID   2048
#define HV    512
#define VO    256

// ---------------------------------------------------------------------------
// Device-global scratch (no cudaMalloc allowed)
// ---------------------------------------------------------------------------
__device__ __align__(256) float g_sq[2 * BATCH];   // [||Yx||^2 ; ||Y1||^2] (atomic)
__device__ __align__(256) float g_sf[BATCH];       // ||FH||^2 (atomic)
__device__ __align__(256) float g_sx[BATCH];       // ||x||^2

// activations, bf16
__device__ __align__(256) __nv_bfloat16 g_AFH[2 * BATCH * DIM];  // [xhi ; FHhi]
__device__ __align__(256) __nv_bfloat16 g_xlo[BATCH * DIM];
__device__ __align__(256) __nv_bfloat16 g_H1hi[BATCH * HID];
__device__ __align__(256) __nv_bfloat16 g_H1lo[BATCH * HID];
__device__ __align__(256) __nv_bfloat16 g_HXT[2 * BATCH * HV];   // [HX ; tanh(U)]

// weights: transposed [N,K], bf16 hi/lo
__device__ __align__(256) __nv_bfloat16 g_W1t_hi[HID * DIM];
__device__ __align__(256) __nv_bfloat16 g_W1t_lo[HID * DIM];
__device__ __align__(256) __nv_bfloat16 g_W2t_hi[DIM * HID];
__device__ __align__(256) __nv_bfloat16 g_W2t_lo[DIM * HID];
__device__ __align__(256) __nv_bfloat16 g_Wv1t_hi[HV * DIM];
__device__ __align__(256) __nv_bfloat16 g_Wv1t_lo[HV * DIM];
__device__ __align__(256) __nv_bfloat16 g_Wv2t_hi[VO * HV];

// ---------------------------------------------------------------------------
// Helpers
// ---------------------------------------------------------------------------
__device__ __forceinline__ uint32_t smem_u32(const void* p) {
    uint32_t a;
    asm("{ .reg .u64 t; cvta.to.shared.u64 t, %1; cvt.u32.u64 %0, t; }"
        : "=r"(a) : "l"(p));
    return a;
}
__device__ __forceinline__ void ldsm4(uint32_t* r, uint32_t addr) {
    asm volatile("ldmatrix.sync.aligned.m8n8.x4.shared.b16 {%0,%1,%2,%3}, [%4];"
                 : "=r"(r[0]), "=r"(r[1]), "=r"(r[2]), "=r"(r[3]) : "r"(addr));
}
__device__ __forceinline__ void mma_bf16(float* c, const uint32_t* a, const uint32_t* b) {
    asm volatile("mma.sync.aligned.m16n8k16.row.col.f32.bf16.bf16.f32 "
                 "{%0,%1,%2,%3}, {%4,%5,%6,%7}, {%8,%9}, {%0,%1,%2,%3};"
                 : "+f"(c[0]), "+f"(c[1]), "+f"(c[2]), "+f"(c[3])
                 : "r"(a[0]), "r"(a[1]), "r"(a[2]), "r"(a[3]),
                   "r"(b[0]), "r"(b[1]));
}
__device__ __forceinline__ void cpa16(uint32_t dst, const void* src) {
    asm volatile("cp.async.cg.shared.global [%0], [%1], 16;" :: "r"(dst), "l"(src));
}
#define CP_COMMIT() asm volatile("cp.async.commit_group;" ::: "memory")
#define CP_WAIT(n)  asm volatile("cp.async.wait_group %0;" :: "n"(n) : "memory")

// SMEM swizzle for 64-byte rows (32 bf16): chunk = 16B unit
__device__ __forceinline__ uint32_t sw_off(int row, int kc) {
    return (uint32_t)(row * 64 + (((kc) ^ ((row >> 1) & 3)) << 4));
}
__device__ __forceinline__ uint32_t pack_bf2(float a, float b) {
    __nv_bfloat162 h = __floats2bfloat162_rn(a, b);
    return *reinterpret_cast<uint32_t*>(&h);
}
__device__ __forceinline__ float bf_hi(float v) {
    return __bfloat162float(__float2bfloat16_rn(v));
}
__device__ __forceinline__ float warpsum(float v) {
    #pragma unroll
    for (int o = 16; o > 0; o >>= 1) v += __shfl_down_sync(0xFFFFFFFFu, v, o);
    return v;
}

// ---------------------------------------------------------------------------
// Fused prep kernel: weight transpose/splits, x split + ||x||^2, zero-init.
// ---------------------------------------------------------------------------
__device__ __forceinline__ void tsplit_body(
    const float* __restrict__ W, int K, int N,
    __nv_bfloat16* __restrict__ hi, __nv_bfloat16* __restrict__ lo,
    int bx, int by, float (*t)[33], int tid)
{
    int n0 = bx * 32, k0 = by * 32;
    int tx = tid & 31, ty = tid >> 5;   // 32 x 8
    #pragma unroll
    for (int i = 0; i < 32; i += 8)
        t[ty + i][tx] = W[(size_t)(k0 + ty + i) * N + n0 + tx];
    __syncthreads();
    #pragma unroll
    for (int i = 0; i < 32; i += 8) {
        float v = t[tx][ty + i];
        __nv_bfloat16 h = __float2bfloat16_rn(v);
        hi[(size_t)(n0 + ty + i) * K + k0 + tx] = h;
        if (lo) {
            float rem = v - __bfloat162float(h);
            lo[(size_t)(n0 + ty + i) * K + k0 + tx] = __float2bfloat16_rn(rem);
        }
    }
}

__global__ void prep_kernel(const float* __restrict__ x,
                            const float* __restrict__ W1,
                            const float* __restrict__ W2,
                            const float* __restrict__ Wv1,
                            const float* __restrict__ Wv2)
{
    __shared__ float t[32][33];
    __shared__ float sred[8];
    const int b = blockIdx.x, tid = threadIdx.x;
    const int lane = tid & 31, wid = tid >> 5;
    if (b < 1024) {
        tsplit_body(W1, DIM, HID, g_W1t_hi, g_W1t_lo, b & 63, b >> 6, t, tid);
    } else if (b < 2048) {
        int r = b - 1024;
        tsplit_body(W2, HID, DIM, g_W2t_hi, g_W2t_lo, r & 15, r >> 4, t, tid);
    } else if (b < 2304) {
        int r = b - 2048;
        tsplit_body(Wv1, DIM, HV, g_Wv1t_hi, g_Wv1t_lo, r & 15, r >> 4, t, tid);
    } else if (b < 2432) {
        int r = b - 2304;
        tsplit_body(Wv2, HV, VO, g_Wv2t_hi, 0, r & 7, r >> 3, t, tid);
    } else if (b < 6528) {
        int i = (b - 2432) * 256 + tid;       // float4 index
        float4 v = reinterpret_cast<const float4*>(x)[i];
        uint2 hp, lp;
        hp.x = pack_bf2(v.x, v.y); hp.y = pack_bf2(v.z, v.w);
        lp.x = pack_bf2(v.x - bf_hi(v.x), v.y - bf_hi(v.y));
        lp.y = pack_bf2(v.z - bf_hi(v.z), v.w - bf_hi(v.w));
        reinterpret_cast<uint2*>(g_AFH)[i] = hp;
        reinterpret_cast<uint2*>(g_xlo)[i] = lp;
        float ss = v.x * v.x + v.y * v.y + v.z * v.z + v.w * v.w;
        ss = warpsum(ss);
        if (lane == 0) sred[wid] = ss;
        __syncthreads();
        if (tid < 2) {
            float s = sred[tid * 4] + sred[tid * 4 + 1]
                    + sred[tid * 4 + 2] + sred[tid * 4 + 3];
            g_sx[(b - 2432) * 2 + tid] = s;
        }
    } else if (b < 6544) {
        reinterpret_cast<float4*>(g_sq)[(b - 6528) * 256 + tid] =
            make_float4(0.f, 0.f, 0.f, 0.f);
    } else {
        reinterpret_cast<float4*>(g_sf)[(b - 6544) * 256 + tid] =
            make_float4(0.f, 0.f, 0.f, 0.f);
    }
}

// ---------------------------------------------------------------------------
// mma.sync GEMM body (device function, runtime tile coords + pointers).
// PASSES=3: hi*hi + hi*lo + lo*hi, BK=32/stage; PASSES=1: hi*hi, BK=64/stage.
// 3 stages x 32 KB, invariant ldsm offsets, incremental global pointers.
// EPI bits: 1=tanh, 2=bias, 4=fp32 Cf, 8=hi/lo split, 16=hi only,
//           256 = row-sumsq atomically into Cf (no other store),
//           512 = row-sumsq atomically into g_sf (plus normal stores)
// ---------------------------------------------------------------------------
#define BKT 32

template <int PASSES, int EPI>
__device__ __forceinline__ void tgemm_body(
    int N, int K,
    const __nv_bfloat16* __restrict__ Ahi,
    const __nv_bfloat16* __restrict__ Alo,
    const __nv_bfloat16* __restrict__ Bhi,
    const __nv_bfloat16* __restrict__ Blo,
    const float* __restrict__ bias,
    float* __restrict__ Cf,
    __nv_bfloat16* __restrict__ Chi,
    __nv_bfloat16* __restrict__ Clo,
    int m0, int n0, char* smem)
{
    constexpr int KSUB  = (PASSES == 3) ? 1 : 2;
    constexpr int S_AHI = 0;
    constexpr int S_ALO = 8192;
    constexpr int S_BHI = (PASSES == 3) ? 16384 : 8192;
    constexpr int S_BLO = 24576;
    constexpr int SUBST = 16384;
    constexpr int STG   = 32768;
    constexpr int NSTG  = 3;

    const uint32_t sb = smem_u32(smem);
    const int tid = threadIdx.x, lane = tid & 31, wid = tid >> 5;
    const int wm = wid & 3, wn = wid >> 2;
    const int nk = K / (BKT * KSUB);

    const int t_row0 = tid >> 2, t_row1 = t_row0 + 64, t_kc = tid & 3;

    const __nv_bfloat16* pA0 = Ahi + (size_t)(m0 + t_row0) * K + t_kc * 8;
    const __nv_bfloat16* pA1 = Ahi + (size_t)(m0 + t_row1) * K + t_kc * 8;
    const __nv_bfloat16* pB0 = Bhi + (size_t)(n0 + t_row0) * K + t_kc * 8;
    const __nv_bfloat16* pB1 = Bhi + (size_t)(n0 + t_row1) * K + t_kc * 8;
    const __nv_bfloat16* pA0l = 0; const __nv_bfloat16* pA1l = 0;
    const __nv_bfloat16* pB0l = 0; const __nv_bfloat16* pB1l = 0;
    if (PASSES == 3) {
        pA0l = Alo + (size_t)(m0 + t_row0) * K + t_kc * 8;
        pA1l = Alo + (size_t)(m0 + t_row1) * K + t_kc * 8;
        pB0l = Blo + (size_t)(n0 + t_row0) * K + t_kc * 8;
        pB1l = Blo + (size_t)(n0 + t_row1) * K + t_kc * 8;
    }
    const uint32_t so0 = sw_off(t_row0, t_kc);
    const uint32_t so1 = sw_off(t_row1, t_kc);

    uint32_t offA[2][2], offB[2][4];
    #pragma unroll
    for (int k16 = 0; k16 < 2; k16++) {
        #pragma unroll
        for (int mt = 0; mt < 2; mt++)
            offA[k16][mt] = sw_off(wm * 32 + mt * 16 + (lane & 15),
                                   k16 * 2 + (lane >> 4));
        #pragma unroll
        for (int g = 0; g < 4; g++)
            offB[k16][g] = sw_off(wn * 64 + g * 16 + ((lane >> 4) << 3) + (lane & 7),
                                  k16 * 2 + ((lane >> 3) & 1));
    }

    float acc[2][8][4];
    #pragma unroll
    for (int i = 0; i < 2; i++)
        #pragma unroll
        for (int j = 0; j < 8; j++)
            #pragma unroll
            for (int q = 0; q < 4; q++) acc[i][j][q] = 0.f;

    int koff = 0, pstg = 0;
    auto issue = [&]() {
        const uint32_t sbuf = sb + (uint32_t)pstg * STG;
        pstg = (pstg + 1 == NSTG) ? 0 : pstg + 1;
        #pragma unroll
        for (int sub = 0; sub < KSUB; sub++) {
            const int k0 = koff + sub * BKT;
            const uint32_t s2 = sbuf + sub * SUBST;
            cpa16(s2 + S_AHI + so0, pA0 + k0);
            cpa16(s2 + S_AHI + so1, pA1 + k0);
            cpa16(s2 + S_BHI + so0, pB0 + k0);
            cpa16(s2 + S_BHI + so1, pB1 + k0);
            if (PASSES == 3) {
                cpa16(s2 + S_ALO + so0, pA0l + k0);
                cpa16(s2 + S_ALO + so1, pA1l + k0);
                cpa16(s2 + S_BLO + so0, pB0l + k0);
                cpa16(s2 + S_BLO + so1, pB1l + k0);
            }
        }
        koff += BKT * KSUB;
        CP_COMMIT();
    };

    #pragma unroll
    for (int p = 0; p < NSTG - 1; p++) issue();

    int cstg = 0;
    for (int c = 0; c < nk; c++) {
        if (c + NSTG - 1 < nk) { CP_WAIT(NSTG - 2); } else { CP_WAIT(0); }
        __syncthreads();
        if (c + NSTG - 1 < nk) issue();

        const uint32_t sbase = sb + (uint32_t)cstg * STG;
        cstg = (cstg + 1 == NSTG) ? 0 : cstg + 1;
        #pragma unroll
        for (int sub = 0; sub < KSUB; sub++) {
            const uint32_t sbase2 = sbase + sub * SUBST;
            #pragma unroll
            for (int k16 = 0; k16 < 2; k16++) {
                uint32_t ah[2][4], al[2][4];
                #pragma unroll
                for (int mt = 0; mt < 2; mt++) {
                    ldsm4(ah[mt], sbase2 + S_AHI + offA[k16][mt]);
                    if (PASSES == 3) ldsm4(al[mt], sbase2 + S_ALO + offA[k16][mt]);
                }
                #pragma unroll
                for (int g = 0; g < 4; g++) {
                    uint32_t bh[4], bl[4];
                    ldsm4(bh, sbase2 + S_BHI + offB[k16][g]);
                    if (PASSES == 3) ldsm4(bl, sbase2 + S_BLO + offB[k16][g]);
                    #pragma unroll
                    for (int mt = 0; mt < 2; mt++) {
                        #pragma unroll
                        for (int h = 0; h < 2; h++) {
                            float* cc = acc[mt][g * 2 + h];
                            mma_bf16(cc, ah[mt], bh + h * 2);
                            if (PASSES == 3) {
                                mma_bf16(cc, ah[mt], bl + h * 2);
                                mma_bf16(cc, al[mt], bh + h * 2);
                            }
                        }
                    }
                }
            }
        }
    }

    // epilogue
    float rs[2][2] = {{0.f, 0.f}, {0.f, 0.f}};
    #pragma unroll
    for (int mt = 0; mt < 2; mt++) {
        #pragma unroll
        for (int nt = 0; nt < 8; nt++) {
            int row = m0 + wm * 32 + mt * 16 + (lane >> 2);
            int col = n0 + wn * 64 + nt * 8 + (lane & 3) * 2;
            float b0 = 0.f, b1v = 0.f;
            if (EPI & 2) { b0 = __ldg(bias + col); b1v = __ldg(bias + col + 1); }
            float v0 = acc[mt][nt][0] + b0, v1 = acc[mt][nt][1] + b1v;
            float v2 = acc[mt][nt][2] + b0, v3 = acc[mt][nt][3] + b1v;
            if (EPI & 1) { v0 = tanhf(v0); v1 = tanhf(v1); v2 = tanhf(v2); v3 = tanhf(v3); }
            if (EPI & (256 | 512)) {
                rs[mt][0] += v0 * v0 + v1 * v1;
                rs[mt][1] += v2 * v2 + v3 * v3;
            }
            size_t o0 = (size_t)row * N + col;
            size_t o1 = (size_t)(row + 8) * N + col;
            if (EPI & 4) {
                *reinterpret_cast<float2*>(Cf + o0) = make_float2(v0, v1);
                *reinterpret_cast<float2*>(Cf + o1) = make_float2(v2, v3);
            }
            if (EPI & (8 | 16)) {
                *reinterpret_cast<uint32_t*>(Chi + o0) = pack_bf2(v0, v1);
                *reinterpret_cast<uint32_t*>(Chi + o1) = pack_bf2(v2, v3);
            }
            if (EPI & 8) {
                *reinterpret_cast<uint32_t*>(Clo + o0) =
                    pack_bf2(v0 - bf_hi(v0), v1 - bf_hi(v1));
                *reinterpret_cast<uint32_t*>(Clo + o1) =
                    pack_bf2(v2 - bf_hi(v2), v3 - bf_hi(v3));
            }
        }
    }
    if (EPI & (256 | 512)) {
        float* dst = (EPI & 256) ? Cf : g_sf;   // EPI 256: Cf is the atomic dst
        #pragma unroll
        for (int mt = 0; mt < 2; mt++) {
            #pragma unroll
            for (int hh = 0; hh < 2; hh++) {
                float s = rs[mt][hh];
                s += __shfl_xor_sync(0xFFFFFFFFu, s, 1);
                s += __shfl_xor_sync(0xFFFFFFFFu, s, 2);
                if ((lane & 3) == 0) {
                    int row = m0 + wm * 32 + mt * 16 + (lane >> 2) + hh * 8;
                    atomicAdd(dst + row, s);
                }
            }
        }
    }
}

// ---------------------------------------------------------------------------
// GEMM launch wrappers (dual kernels pack independent GEMMs into idle slots)
// ---------------------------------------------------------------------------
__global__ __launch_bounds__(256, 2) void g1_kernel(const float* __restrict__ b1)
{
    extern __shared__ char smem[];
    tgemm_body<3, 1 | 2 | 8>(HID, DIM, g_AFH, g_xlo, g_W1t_hi, g_W1t_lo, b1,
                             0, g_H1hi, g_H1lo,
                             blockIdx.y * 128, blockIdx.x * 128, smem);
}

// G2 (bx<4): out(=FH)+FHhi = H1@W2+b2, sf reduce  [3-pass]
// G3 (bx>=4): HX = tanh(x@Wv1)                    [1-pass]  (independent)
__global__ __launch_bounds__(256, 2) void g2g3_kernel(const float* __restrict__ b2,
                                                      float* __restrict__ out)
{
    extern __shared__ char smem[];
    if (blockIdx.x < 4) {
        tgemm_body<3, 2 | 4 | 16 | 512>(DIM, HID, g_H1hi, g_H1lo, g_W2t_hi, g_W2t_lo,
                                        b2, out, g_AFH + (size_t)BATCH * DIM, 0,
                                        blockIdx.y * 128, blockIdx.x * 128, smem);
    } else {
        tgemm_body<1, 1 | 16>(HV, DIM, g_AFH, 0, g_Wv1t_hi, 0, 0,
                              0, g_HXT, 0,
                              blockIdx.y * 128, (blockIdx.x - 4) * 128, smem);
    }
}

// G5 (bx<4): T = tanh(FH@Wv1)                     [1-pass]
// G46a (bx>=4): rowsq(HX@Wv2) -> g_sq[0:B)        [1-pass]  (independent)
__global__ __launch_bounds__(256, 2) void g5g4_kernel()
{
    extern __shared__ char smem[];
    if (blockIdx.x < 4) {
        tgemm_body<1, 1 | 16>(HV, DIM, g_AFH + (size_t)BATCH * DIM, 0, g_Wv1t_hi, 0,
                              0, 0, g_HXT + (size_t)BATCH * HV, 0,
                              blockIdx.y * 128, blockIdx.x * 128, smem);
    } else {
        tgemm_body<1, 256>(VO, HV, g_HXT, 0, g_Wv2t_hi, 0, 0,
                           g_sq, 0, 0,
                           blockIdx.y * 128, (blockIdx.x - 4) * 128, smem);
    }
}

// G46b: rowsq(T@Wv2) -> g_sq[B:2B)                [1-pass]
__global__ __launch_bounds__(256, 2) void g6_kernel()
{
    extern __shared__ char smem[];
    tgemm_body<1, 256>(VO, HV, g_HXT + (size_t)BATCH * HV, 0, g_Wv2t_hi, 0, 0,
                       g_sq + BATCH, 0, 0,
                       blockIdx.y * 128, blockIdx.x * 128, smem);
}

// ---------------------------------------------------------------------------
// Newton rootfind: scalar residual check; alpha=1 fast path is a no-op
// (out already holds FH from G2). Slow path recomputes u = FH@Wv1 in fp32,
// runs the exact masked Newton loop, scales out in place.
// ---------------------------------------------------------------------------
#define NG 8
__global__ __launch_bounds__(256) void newton_kernel(const float* __restrict__ Wv1,
                                                     const float* __restrict__ Wv2,
                                                     float* __restrict__ out)
{
    __shared__ float sh_h[NG][HV];
    __shared__ float sh_u[NG][HV];
    __shared__ float sh_part[8][NG];
    __shared__ float sh_alpha[NG], sh_resid[NG], sh_s[NG], sh_tgt[NG];
    __shared__ int   sh_active[NG], sh_upd[NG], sh_any;

    const int tid  = threadIdx.x;
    const int lane = tid & 31, wid = tid >> 5;
    const int base = blockIdx.x * NG;
    const int b4   = base * (DIM / 4);

    if (tid < NG) {
        int row = base + tid;
        float tgt = 0.99f * (g_sq[row] + 0.01f * g_sx[row]);
        float sf  = g_sf[row];
        float resid = (g_sq[BATCH + row] + 0.01f * sf) - tgt;
        sh_tgt[tid]    = tgt;
        sh_s[tid]      = sf;
        sh_active[tid] = (resid > 1e-3f) ? 1 : 0;
        sh_alpha[tid]  = 1.0f;
    }
    __syncthreads();
    if (tid == 0) {
        int a = 0;
        #pragma unroll
        for (int s2 = 0; s2 < NG; s2++) a |= sh_active[s2];
        sh_any = a;
    }
    __syncthreads();
    if (!sh_any) return;   // out already == FH (alpha = 1 everywhere)

    // slow path: recompute u = FH@Wv1 in fp32 (FH lives in `out`)
    for (int idx = tid; idx < NG * (DIM / 4); idx += 256) {
        int sI = idx >> 7, v = idx & 127;
        reinterpret_cast<float4*>(sh_h[sI])[v] =
            reinterpret_cast<const float4*>(out + (size_t)(base + sI) * DIM)[v];
    }
    __syncthreads();
    for (int k = tid; k < HV; k += 256) {
        float accu[NG];
        #pragma unroll
        for (int s2 = 0; s2 < NG; s2++) accu[s2] = 0.f;
        for (int d = 0; d < DIM; d++) {
            float w = Wv1[(size_t)d * HV + k];
            #pragma unroll
            for (int s2 = 0; s2 < NG; s2++) accu[s2] += sh_h[s2][d] * w;
        }
        #pragma unroll
        for (int s2 = 0; s2 < NG; s2++) sh_u[s2][k] = accu[s2];
    }
    __syncthreads();

    for (int it = 0; it < 50; it++) {
        for (int idx = tid; idx < NG * HV; idx += 256) {
            int sI = idx >> 9, k = idx & (HV - 1);
            if (sh_active[sI]) sh_h[sI][k] = tanhf(sh_alpha[sI] * sh_u[sI][k]);
        }
        __syncthreads();

        float accY[NG];
        #pragma unroll
        for (int s2 = 0; s2 < NG; s2++) accY[s2] = 0.f;
        const int j = tid;
        for (int k = 0; k < HV; k += 4) {
            float w0 = Wv2[(k + 0) * VO + j];
            float w1 = Wv2[(k + 1) * VO + j];
            float w2 = Wv2[(k + 2) * VO + j];
            float w3 = Wv2[(k + 3) * VO + j];
            #pragma unroll
            for (int s2 = 0; s2 < NG; s2++) {
                float4 hv = *reinterpret_cast<const float4*>(&sh_h[s2][k]);
                accY[s2] += hv.x * w0 + hv.y * w1 + hv.z * w2 + hv.w * w3;
            }
        }
        #pragma unroll
        for (int s2 = 0; s2 < NG; s2++) {
            float v = warpsum(accY[s2] * accY[s2]);
            if (lane == 0) sh_part[wid][s2] = v;
        }
        __syncthreads();
        if (tid < NG) {
            sh_upd[tid] = 0;
            if (sh_active[tid]) {
                float Vz = 0.f;
                #pragma unroll
                for (int w = 0; w < 8; w++) Vz += sh_part[w][tid];
                float a = sh_alpha[tid];
                Vz += 0.01f * a * a * sh_s[tid];
                float resid = Vz - sh_tgt[tid];
                if (resid > 1e-3f) { sh_upd[tid] = 1; sh_resid[tid] = resid; }
                else               sh_active[tid] = 0;
            }
        }
        __syncthreads();
        if (tid == 0) {
            int a = 0;
            #pragma unroll
            for (int s2 = 0; s2 < NG; s2++) a |= sh_upd[s2];
            sh_any = a;
        }
        __syncthreads();
        if (!sh_any) break;

        float accW[NG];
        #pragma unroll
        for (int s2 = 0; s2 < NG; s2++) accW[s2] = 0.f;
        for (int k = 0; k < HV; k += 4) {
            float w0 = Wv2[(k + 0) * VO + j];
            float w1 = Wv2[(k + 1) * VO + j];
            float w2 = Wv2[(k + 2) * VO + j];
            float w3 = Wv2[(k + 3) * VO + j];
            #pragma unroll
            for (int s2 = 0; s2 < NG; s2++) {
                float4 hv = *reinterpret_cast<const float4*>(&sh_h[s2][k]);
                float4 uv = *reinterpret_cast<const float4*>(&sh_u[s2][k]);
                accW[s2] += (1.f - hv.x * hv.x) * uv.x * w0
                          + (1.f - hv.y * hv.y) * uv.y * w1
                          + (1.f - hv.z * hv.z) * uv.z * w2
                          + (1.f - hv.w * hv.w) * uv.w * w3;
            }
        }
        #pragma unroll
        for (int s2 = 0; s2 < NG; s2++) {
            float v = warpsum(accY[s2] * accW[s2]);
            if (lane == 0) sh_part[wid][s2] = v;
        }
        __syncthreads();
        if (tid < NG && sh_upd[tid]) {
            float dot = 0.f;
            #pragma unroll
            for (int w = 0; w < 8; w++) dot += sh_part[w][tid];
            float a   = sh_alpha[tid];
            float dVda = 2.f * dot + 0.02f * a * sh_s[tid];
            sh_alpha[tid] = a - sh_resid[tid] / dVda;
        }
        __syncthreads();
    }

    // out *= alpha (per-row; alpha==1 rows unchanged)
    #pragma unroll
    for (int i = 0; i < NG * (DIM / 4) / 256; i++) {
        int idx = i * 256 + tid;
        float a = sh_alpha[idx >> 7];
        float4 v = reinterpret_cast<float4*>(out)[b4 + idx];
        v.x *= a; v.y *= a; v.z *= a; v.w *= a;
        reinterpret_cast<float4*>(out)[b4 + idx] = v;
    }
}

// ---------------------------------------------------------------------------
extern "C" void kernel_launch(void* const* d_in, const int* in_sizes, int n_in,
                              void* d_out, int out_size)
{
    const float* x   = (const float*)d_in[0];
    const float* W1  = (const float*)d_in[1];
    const float* b1  = (const float*)d_in[2];
    const float* W2  = (const float*)d_in[3];
    const float* b2  = (const float*)d_in[4];
    const float* Wv1 = (const float*)d_in[5];
    const float* Wv2 = (const float*)d_in[6];
    float* out = (float*)d_out;

    cudaFuncSetAttribute(g1_kernel,   cudaFuncAttributeMaxDynamicSharedMemorySize, 98304);
    cudaFuncSetAttribute(g2g3_kernel, cudaFuncAttributeMaxDynamicSharedMemorySize, 98304);
    cudaFuncSetAttribute(g5g4_kernel, cudaFuncAttributeMaxDynamicSharedMemorySize, 98304);
    cudaFuncSetAttribute(g6_kernel,   cudaFuncAttributeMaxDynamicSharedMemorySize, 98304);

    // #1: fused prep (weight splits + x split + ||x||^2 + zero-init)
    prep_kernel<<<6552, 256>>>(x, W1, W2, Wv1, Wv2);
    // #2: G1: H1(hi/lo) = tanh(x@W1 + b1)              [3-pass]
    g1_kernel<<<dim3(HID / 128, BATCH / 128), 256, 98304>>>(b1);
    // #3: G2 + G3 packed (G3 rides G2's idle CTA slots)
    g2g3_kernel<<<dim3(DIM / 128 + HV / 128, BATCH / 128), 256, 98304>>>(b2, out);
    // #4: G5 + G46a packed (G46a rides G5's idle CTA slots)
    g5g4_kernel<<<dim3(HV / 128 + VO / 128, BATCH / 128), 256, 98304>>>();
    // #5: G46b: rowsq(T@Wv2) -> g_sq[B:2B)
    g6_kernel<<<dim3(VO / 128, BATCH / 128), 256, 98304>>>();
    // #6: newton (scalar residual check; out scaled in place only if needed)
    newton_kernel<<<BATCH / NG, 256>>>(Wv1, Wv2, out);
}

// round 16
// speedup vs baseline: 1.0255x; 1.0255x over previous
#include <cuda_runtime.h>
#include <cuda_bf16.h>
#include <stdint.h>
#include <math.h>

// Problem constants
#define BATCH 8192
#define DIM   512
#define HID   2048
#define HV    512
#define VO    256

// ---------------------------------------------------------------------------
// Device-global scratch (no cudaMalloc allowed)
// ---------------------------------------------------------------------------
__device__ __align__(256) float g_sq[2 * BATCH];   // [||Yx||^2 ; ||Y1||^2] (atomic)
__device__ __align__(256) float g_sf[BATCH];       // ||FH||^2 (atomic)
__device__ __align__(256) float g_sx[BATCH];       // ||x||^2

// activations, bf16
__device__ __align__(256) __nv_bfloat16 g_AFH[2 * BATCH * DIM];  // [xhi ; FHhi]
__device__ __align__(256) __nv_bfloat16 g_xlo[BATCH * DIM];
__device__ __align__(256) __nv_bfloat16 g_H1hi[BATCH * HID];
__device__ __align__(256) __nv_bfloat16 g_H1lo[BATCH * HID];
__device__ __align__(256) __nv_bfloat16 g_HXT[2 * BATCH * HV];   // [HX ; tanh(U)]

// weights: transposed [N,K], bf16 hi/lo
__device__ __align__(256) __nv_bfloat16 g_W1t_hi[HID * DIM];
__device__ __align__(256) __nv_bfloat16 g_W1t_lo[HID * DIM];
__device__ __align__(256) __nv_bfloat16 g_W2t_hi[DIM * HID];
__device__ __align__(256) __nv_bfloat16 g_W2t_lo[DIM * HID];
__device__ __align__(256) __nv_bfloat16 g_Wv1t_hi[HV * DIM];
__device__ __align__(256) __nv_bfloat16 g_Wv1t_lo[HV * DIM];
__device__ __align__(256) __nv_bfloat16 g_Wv2t_hi[VO * HV];

// ---------------------------------------------------------------------------
// Helpers
// ---------------------------------------------------------------------------
__device__ __forceinline__ uint32_t smem_u32(const void* p) {
    uint32_t a;
    asm("{ .reg .u64 t; cvta.to.shared.u64 t, %1; cvt.u32.u64 %0, t; }"
        : "=r"(a) : "l"(p));
    return a;
}
__device__ __forceinline__ void ldsm4(uint32_t* r, uint32_t addr) {
    asm volatile("ldmatrix.sync.aligned.m8n8.x4.shared.b16 {%0,%1,%2,%3}, [%4];"
                 : "=r"(r[0]), "=r"(r[1]), "=r"(r[2]), "=r"(r[3]) : "r"(addr));
}
__device__ __forceinline__ void mma_bf16(float* c, const uint32_t* a, const uint32_t* b) {
    asm volatile("mma.sync.aligned.m16n8k16.row.col.f32.bf16.bf16.f32 "
                 "{%0,%1,%2,%3}, {%4,%5,%6,%7}, {%8,%9}, {%0,%1,%2,%3};"
                 : "+f"(c[0]), "+f"(c[1]), "+f"(c[2]), "+f"(c[3])
                 : "r"(a[0]), "r"(a[1]), "r"(a[2]), "r"(a[3]),
                   "r"(b[0]), "r"(b[1]));
}
__device__ __forceinline__ void cpa16(uint32_t dst, const void* src) {
    asm volatile("cp.async.cg.shared.global [%0], [%1], 16;" :: "r"(dst), "l"(src));
}
#define CP_COMMIT() asm volatile("cp.async.commit_group;" ::: "memory")
#define CP_WAIT(n)  asm volatile("cp.async.wait_group %0;" :: "n"(n) : "memory")

// SMEM swizzle for 64-byte rows (32 bf16): chunk = 16B unit
__device__ __forceinline__ uint32_t sw_off(int row, int kc) {
    return (uint32_t)(row * 64 + (((kc) ^ ((row >> 1) & 3)) << 4));
}
__device__ __forceinline__ uint32_t pack_bf2(float a, float b) {
    __nv_bfloat162 h = __floats2bfloat162_rn(a, b);
    return *reinterpret_cast<uint32_t*>(&h);
}
__device__ __forceinline__ float bf_hi(float v) {
    return __bfloat162float(__float2bfloat16_rn(v));
}
__device__ __forceinline__ float warpsum(float v) {
    #pragma unroll
    for (int o = 16; o > 0; o >>= 1) v += __shfl_down_sync(0xFFFFFFFFu, v, o);
    return v;
}

// ---------------------------------------------------------------------------
// Fused prep kernel: weight transpose/splits, x split + ||x||^2, zero-init.
// ---------------------------------------------------------------------------
__device__ __forceinline__ void tsplit_body(
    const float* __restrict__ W, int K, int N,
    __nv_bfloat16* __restrict__ hi, __nv_bfloat16* __restrict__ lo,
    int bx, int by, float (*t)[33], int tid)
{
    int n0 = bx * 32, k0 = by * 32;
    int tx = tid & 31, ty = tid >> 5;   // 32 x 8
    #pragma unroll
    for (int i = 0; i < 32; i += 8)
        t[ty + i][tx] = W[(size_t)(k0 + ty + i) * N + n0 + tx];
    __syncthreads();
    #pragma unroll
    for (int i = 0; i < 32; i += 8) {
        float v = t[tx][ty + i];
        __nv_bfloat16 h = __float2bfloat16_rn(v);
        hi[(size_t)(n0 + ty + i) * K + k0 + tx] = h;
        if (lo) {
            float rem = v - __bfloat162float(h);
            lo[(size_t)(n0 + ty + i) * K + k0 + tx] = __float2bfloat16_rn(rem);
        }
    }
}

__global__ void prep_kernel(const float* __restrict__ x,
                            const float* __restrict__ W1,
                            const float* __restrict__ W2,
                            const float* __restrict__ Wv1,
                            const float* __restrict__ Wv2,
                            __nv_bfloat16* __restrict__ xhi,
                            __nv_bfloat16* __restrict__ xlo,
                            __nv_bfloat16* __restrict__ W1h, __nv_bfloat16* __restrict__ W1l,
                            __nv_bfloat16* __restrict__ W2h, __nv_bfloat16* __restrict__ W2l,
                            __nv_bfloat16* __restrict__ V1h, __nv_bfloat16* __restrict__ V1l,
                            __nv_bfloat16* __restrict__ V2h)
{
    __shared__ float t[32][33];
    __shared__ float sred[8];
    const int b = blockIdx.x, tid = threadIdx.x;
    const int lane = tid & 31, wid = tid >> 5;
    if (b < 1024) {
        tsplit_body(W1, DIM, HID, W1h, W1l, b & 63, b >> 6, t, tid);
    } else if (b < 2048) {
        int r = b - 1024;
        tsplit_body(W2, HID, DIM, W2h, W2l, r & 15, r >> 4, t, tid);
    } else if (b < 2304) {
        int r = b - 2048;
        tsplit_body(Wv1, DIM, HV, V1h, V1l, r & 15, r >> 4, t, tid);
    } else if (b < 2432) {
        int r = b - 2304;
        tsplit_body(Wv2, HV, VO, V2h, 0, r & 7, r >> 3, t, tid);
    } else if (b < 6528) {
        int i = (b - 2432) * 256 + tid;       // float4 index
        float4 v = reinterpret_cast<const float4*>(x)[i];
        uint2 hp, lp;
        hp.x = pack_bf2(v.x, v.y); hp.y = pack_bf2(v.z, v.w);
        lp.x = pack_bf2(v.x - bf_hi(v.x), v.y - bf_hi(v.y));
        lp.y = pack_bf2(v.z - bf_hi(v.z), v.w - bf_hi(v.w));
        reinterpret_cast<uint2*>(xhi)[i] = hp;
        reinterpret_cast<uint2*>(xlo)[i] = lp;
        float ss = v.x * v.x + v.y * v.y + v.z * v.z + v.w * v.w;
        ss = warpsum(ss);
        if (lane == 0) sred[wid] = ss;
        __syncthreads();
        if (tid < 2) {
            float s = sred[tid * 4] + sred[tid * 4 + 1]
                    + sred[tid * 4 + 2] + sred[tid * 4 + 3];
            g_sx[(b - 2432) * 2 + tid] = s;
        }
    } else if (b < 6544) {
        reinterpret_cast<float4*>(g_sq)[(b - 6528) * 256 + tid] =
            make_float4(0.f, 0.f, 0.f, 0.f);
    } else {
        reinterpret_cast<float4*>(g_sf)[(b - 6544) * 256 + tid] =
            make_float4(0.f, 0.f, 0.f, 0.f);
    }
}

// ---------------------------------------------------------------------------
// mma.sync GEMM: C[M,N] = epi(A @ Bt^T [+bias]).
// PASSES=3: hi*hi + hi*lo + lo*hi, BK=32/stage; PASSES=1: hi*hi, BK=64/stage.
// 3 stages x 32 KB = 96 KB, 2 CTAs/SM, one __syncthreads per stage.
// Hot loop addressing fully hoisted: invariant ldsm offsets + incremental
// global pointers + explicit stage cycling.
// EPI bits: 1=tanh, 2=bias, 4=fp32 Cf, 8=hi/lo split, 16=hi only,
//           256 = row-sumsq -> g_sq (no store), 512 = also sumsq -> g_sf
// ---------------------------------------------------------------------------
#define BKT 32

template <int PASSES, int EPI>
__global__ __launch_bounds__(256, 2) void tgemm(
    int N, int K,
    const __nv_bfloat16* __restrict__ Ahi,
    const __nv_bfloat16* __restrict__ Alo,
    const __nv_bfloat16* __restrict__ Bhi,
    const __nv_bfloat16* __restrict__ Blo,
    const float* __restrict__ bias,
    float* __restrict__ Cf,
    __nv_bfloat16* __restrict__ Chi,
    __nv_bfloat16* __restrict__ Clo)
{
    constexpr int KSUB  = (PASSES == 3) ? 1 : 2;
    constexpr int S_AHI = 0;
    constexpr int S_ALO = 8192;
    constexpr int S_BHI = (PASSES == 3) ? 16384 : 8192;
    constexpr int S_BLO = 24576;
    constexpr int SUBST = 16384;
    constexpr int STG   = 32768;
    constexpr int NSTG  = 3;

    extern __shared__ char smem[];
    const uint32_t sb = smem_u32(smem);
    const int tid = threadIdx.x, lane = tid & 31, wid = tid >> 5;
    const int wm = wid & 3, wn = wid >> 2;
    const int m0 = blockIdx.y * 128, n0 = blockIdx.x * 128;
    const int nk = K / (BKT * KSUB);

    const int t_row0 = tid >> 2, t_row1 = t_row0 + 64, t_kc = tid & 3;

    // incremental global pointers + invariant store offsets
    const __nv_bfloat16* pA0 = Ahi + (size_t)(m0 + t_row0) * K + t_kc * 8;
    const __nv_bfloat16* pA1 = Ahi + (size_t)(m0 + t_row1) * K + t_kc * 8;
    const __nv_bfloat16* pB0 = Bhi + (size_t)(n0 + t_row0) * K + t_kc * 8;
    const __nv_bfloat16* pB1 = Bhi + (size_t)(n0 + t_row1) * K + t_kc * 8;
    const __nv_bfloat16* pA0l = 0; const __nv_bfloat16* pA1l = 0;
    const __nv_bfloat16* pB0l = 0; const __nv_bfloat16* pB1l = 0;
    if (PASSES == 3) {
        pA0l = Alo + (size_t)(m0 + t_row0) * K + t_kc * 8;
        pA1l = Alo + (size_t)(m0 + t_row1) * K + t_kc * 8;
        pB0l = Blo + (size_t)(n0 + t_row0) * K + t_kc * 8;
        pB1l = Blo + (size_t)(n0 + t_row1) * K + t_kc * 8;
    }
    const uint32_t so0 = sw_off(t_row0, t_kc);
    const uint32_t so1 = sw_off(t_row1, t_kc);

    // invariant ldsm offsets (2 k16 x {2 A, 4 B})
    uint32_t offA[2][2], offB[2][4];
    #pragma unroll
    for (int k16 = 0; k16 < 2; k16++) {
        #pragma unroll
        for (int mt = 0; mt < 2; mt++)
            offA[k16][mt] = sw_off(wm * 32 + mt * 16 + (lane & 15),
                                   k16 * 2 + (lane >> 4));
        #pragma unroll
        for (int g = 0; g < 4; g++)
            offB[k16][g] = sw_off(wn * 64 + g * 16 + ((lane >> 4) << 3) + (lane & 7),
                                  k16 * 2 + ((lane >> 3) & 1));
    }

    float acc[2][8][4];
    #pragma unroll
    for (int i = 0; i < 2; i++)
        #pragma unroll
        for (int j = 0; j < 8; j++)
            #pragma unroll
            for (int q = 0; q < 4; q++) acc[i][j][q] = 0.f;

    int koff = 0, pstg = 0;
    auto issue = [&]() {
        const uint32_t sbuf = sb + (uint32_t)pstg * STG;
        pstg = (pstg + 1 == NSTG) ? 0 : pstg + 1;
        #pragma unroll
        for (int sub = 0; sub < KSUB; sub++) {
            const int k0 = koff + sub * BKT;
            const uint32_t s2 = sbuf + sub * SUBST;
            cpa16(s2 + S_AHI + so0, pA0 + k0);
            cpa16(s2 + S_AHI + so1, pA1 + k0);
            cpa16(s2 + S_BHI + so0, pB0 + k0);
            cpa16(s2 + S_BHI + so1, pB1 + k0);
            if (PASSES == 3) {
                cpa16(s2 + S_ALO + so0, pA0l + k0);
                cpa16(s2 + S_ALO + so1, pA1l + k0);
                cpa16(s2 + S_BLO + so0, pB0l + k0);
                cpa16(s2 + S_BLO + so1, pB1l + k0);
            }
        }
        koff += BKT * KSUB;
        CP_COMMIT();
    };

    #pragma unroll
    for (int p = 0; p < NSTG - 1; p++) issue();

    int cstg = 0;
    for (int c = 0; c < nk; c++) {
        if (c + NSTG - 1 < nk) { CP_WAIT(NSTG - 2); } else { CP_WAIT(0); }
        __syncthreads();
        if (c + NSTG - 1 < nk) issue();

        const uint32_t sbase = sb + (uint32_t)cstg * STG;
        cstg = (cstg + 1 == NSTG) ? 0 : cstg + 1;
        #pragma unroll
        for (int sub = 0; sub < KSUB; sub++) {
            const uint32_t sbase2 = sbase + sub * SUBST;
            #pragma unroll
            for (int k16 = 0; k16 < 2; k16++) {
                uint32_t ah[2][4], al[2][4];
                #pragma unroll
                for (int mt = 0; mt < 2; mt++) {
                    ldsm4(ah[mt], sbase2 + S_AHI + offA[k16][mt]);
                    if (PASSES == 3) ldsm4(al[mt], sbase2 + S_ALO + offA[k16][mt]);
                }
                #pragma unroll
                for (int g = 0; g < 4; g++) {
                    uint32_t bh[4], bl[4];
                    ldsm4(bh, sbase2 + S_BHI + offB[k16][g]);
                    if (PASSES == 3) ldsm4(bl, sbase2 + S_BLO + offB[k16][g]);
                    #pragma unroll
                    for (int mt = 0; mt < 2; mt++) {
                        #pragma unroll
                        for (int h = 0; h < 2; h++) {
                            float* cc = acc[mt][g * 2 + h];
                            mma_bf16(cc, ah[mt], bh + h * 2);
                            if (PASSES == 3) {
                                mma_bf16(cc, ah[mt], bl + h * 2);
                                mma_bf16(cc, al[mt], bh + h * 2);
                            }
                        }
                    }
                }
            }
        }
    }

    // epilogue
    float rs[2][2] = {{0.f, 0.f}, {0.f, 0.f}};
    #pragma unroll
    for (int mt = 0; mt < 2; mt++) {
        #pragma unroll
        for (int nt = 0; nt < 8; nt++) {
            int row = m0 + wm * 32 + mt * 16 + (lane >> 2);
            int col = n0 + wn * 64 + nt * 8 + (lane & 3) * 2;
            float b0 = 0.f, b1v = 0.f;
            if (EPI & 2) { b0 = __ldg(bias + col); b1v = __ldg(bias + col + 1); }
            float v0 = acc[mt][nt][0] + b0, v1 = acc[mt][nt][1] + b1v;
            float v2 = acc[mt][nt][2] + b0, v3 = acc[mt][nt][3] + b1v;
            if (EPI & 1) { v0 = tanhf(v0); v1 = tanhf(v1); v2 = tanhf(v2); v3 = tanhf(v3); }
            if (EPI & (256 | 512)) {
                rs[mt][0] += v0 * v0 + v1 * v1;
                rs[mt][1] += v2 * v2 + v3 * v3;
            }
            size_t o0 = (size_t)row * N + col;
            size_t o1 = (size_t)(row + 8) * N + col;
            if (EPI & 4) {
                *reinterpret_cast<float2*>(Cf + o0) = make_float2(v0, v1);
                *reinterpret_cast<float2*>(Cf + o1) = make_float2(v2, v3);
            }
            if (EPI & (8 | 16)) {
                *reinterpret_cast<uint32_t*>(Chi + o0) = pack_bf2(v0, v1);
                *reinterpret_cast<uint32_t*>(Chi + o1) = pack_bf2(v2, v3);
            }
            if (EPI & 8) {
                *reinterpret_cast<uint32_t*>(Clo + o0) =
                    pack_bf2(v0 - bf_hi(v0), v1 - bf_hi(v1));
                *reinterpret_cast<uint32_t*>(Clo + o1) =
                    pack_bf2(v2 - bf_hi(v2), v3 - bf_hi(v3));
            }
        }
    }
    if (EPI & (256 | 512)) {
        float* dst = (EPI & 256) ? g_sq : g_sf;
        #pragma unroll
        for (int mt = 0; mt < 2; mt++) {
            #pragma unroll
            for (int hh = 0; hh < 2; hh++) {
                float s = rs[mt][hh];
                s += __shfl_xor_sync(0xFFFFFFFFu, s, 1);
                s += __shfl_xor_sync(0xFFFFFFFFu, s, 2);
                if ((lane & 3) == 0) {
                    int row = m0 + wm * 32 + mt * 16 + (lane >> 2) + hh * 8;
                    atomicAdd(dst + row, s);
                }
            }
        }
    }
}

// ---------------------------------------------------------------------------
// Newton rootfind: scalar residual check; alpha=1 fast path is a no-op
// (out already holds FH from G2). Slow path recomputes u = FH@Wv1 in fp32,
// runs the exact masked Newton loop, scales out in place.
// ---------------------------------------------------------------------------
#define NG 8
__global__ __launch_bounds__(256) void newton_kernel(const float* __restrict__ Wv1,
                                                     const float* __restrict__ Wv2,
                                                     float* __restrict__ out)
{
    __shared__ float sh_h[NG][HV];
    __shared__ float sh_u[NG][HV];
    __shared__ float sh_part[8][NG];
    __shared__ float sh_alpha[NG], sh_resid[NG], sh_s[NG], sh_tgt[NG];
    __shared__ int   sh_active[NG], sh_upd[NG], sh_any;

    const int tid  = threadIdx.x;
    const int lane = tid & 31, wid = tid >> 5;
    const int base = blockIdx.x * NG;
    const int b4   = base * (DIM / 4);

    if (tid < NG) {
        int row = base + tid;
        float tgt = 0.99f * (g_sq[row] + 0.01f * g_sx[row]);
        float sf  = g_sf[row];
        float resid = (g_sq[BATCH + row] + 0.01f * sf) - tgt;
        sh_tgt[tid]    = tgt;
        sh_s[tid]      = sf;
        sh_active[tid] = (resid > 1e-3f) ? 1 : 0;
        sh_alpha[tid]  = 1.0f;
    }
    __syncthreads();
    if (tid == 0) {
        int a = 0;
        #pragma unroll
        for (int s2 = 0; s2 < NG; s2++) a |= sh_active[s2];
        sh_any = a;
    }
    __syncthreads();
    if (!sh_any) return;   // out already == FH (alpha = 1 everywhere)

    // slow path: recompute u = FH@Wv1 in fp32 (FH lives in `out`)
    for (int idx = tid; idx < NG * (DIM / 4); idx += 256) {
        int sI = idx >> 7, v = idx & 127;
        reinterpret_cast<float4*>(sh_h[sI])[v] =
            reinterpret_cast<const float4*>(out + (size_t)(base + sI) * DIM)[v];
    }
    __syncthreads();
    for (int k = tid; k < HV; k += 256) {
        float accu[NG];
        #pragma unroll
        for (int s2 = 0; s2 < NG; s2++) accu[s2] = 0.f;
        for (int d = 0; d < DIM; d++) {
            float w = Wv1[(size_t)d * HV + k];
            #pragma unroll
            for (int s2 = 0; s2 < NG; s2++) accu[s2] += sh_h[s2][d] * w;
        }
        #pragma unroll
        for (int s2 = 0; s2 < NG; s2++) sh_u[s2][k] = accu[s2];
    }
    __syncthreads();

    for (int it = 0; it < 50; it++) {
        for (int idx = tid; idx < NG * HV; idx += 256) {
            int sI = idx >> 9, k = idx & (HV - 1);
            if (sh_active[sI]) sh_h[sI][k] = tanhf(sh_alpha[sI] * sh_u[sI][k]);
        }
        __syncthreads();

        float accY[NG];
        #pragma unroll
        for (int s2 = 0; s2 < NG; s2++) accY[s2] = 0.f;
        const int j = tid;
        for (int k = 0; k < HV; k += 4) {
            float w0 = Wv2[(k + 0) * VO + j];
            float w1 = Wv2[(k + 1) * VO + j];
            float w2 = Wv2[(k + 2) * VO + j];
            float w3 = Wv2[(k + 3) * VO + j];
            #pragma unroll
            for (int s2 = 0; s2 < NG; s2++) {
                float4 hv = *reinterpret_cast<const float4*>(&sh_h[s2][k]);
                accY[s2] += hv.x * w0 + hv.y * w1 + hv.z * w2 + hv.w * w3;
            }
        }
        #pragma unroll
        for (int s2 = 0; s2 < NG; s2++) {
            float v = warpsum(accY[s2] * accY[s2]);
            if (lane == 0) sh_part[wid][s2] = v;
        }
        __syncthreads();
        if (tid < NG) {
            sh_upd[tid] = 0;
            if (sh_active[tid]) {
                float Vz = 0.f;
                #pragma unroll
                for (int w = 0; w < 8; w++) Vz += sh_part[w][tid];
                float a = sh_alpha[tid];
                Vz += 0.01f * a * a * sh_s[tid];
                float resid = Vz - sh_tgt[tid];
                if (resid > 1e-3f) { sh_upd[tid] = 1; sh_resid[tid] = resid; }
                else               sh_active[tid] = 0;
            }
        }
        __syncthreads();
        if (tid == 0) {
            int a = 0;
            #pragma unroll
            for (int s2 = 0; s2 < NG; s2++) a |= sh_upd[s2];
            sh_any = a;
        }
        __syncthreads();
        if (!sh_any) break;

        float accW[NG];
        #pragma unroll
        for (int s2 = 0; s2 < NG; s2++) accW[s2] = 0.f;
        for (int k = 0; k < HV; k += 4) {
            float w0 = Wv2[(k + 0) * VO + j];
            float w1 = Wv2[(k + 1) * VO + j];
            float w2 = Wv2[(k + 2) * VO + j];
            float w3 = Wv2[(k + 3) * VO + j];
            #pragma unroll
            for (int s2 = 0; s2 < NG; s2++) {
                float4 hv = *reinterpret_cast<const float4*>(&sh_h[s2][k]);
                float4 uv = *reinterpret_cast<const float4*>(&sh_u[s2][k]);
                accW[s2] += (1.f - hv.x * hv.x) * uv.x * w0
                          + (1.f - hv.y * hv.y) * uv.y * w1
                          + (1.f - hv.z * hv.z) * uv.z * w2
                          + (1.f - hv.w * hv.w) * uv.w * w3;
            }
        }
        #pragma unroll
        for (int s2 = 0; s2 < NG; s2++) {
            float v = warpsum(accY[s2] * accW[s2]);
            if (lane == 0) sh_part[wid][s2] = v;
        }
        __syncthreads();
        if (tid < NG && sh_upd[tid]) {
            float dot = 0.f;
            #pragma unroll
            for (int w = 0; w < 8; w++) dot += sh_part[w][tid];
            float a   = sh_alpha[tid];
            float dVda = 2.f * dot + 0.02f * a * sh_s[tid];
            sh_alpha[tid] = a - sh_resid[tid] / dVda;
        }
        __syncthreads();
    }

    // out *= alpha (per-row; alpha==1 rows unchanged)
    #pragma unroll
    for (int i = 0; i < NG * (DIM / 4) / 256; i++) {
        int idx = i * 256 + tid;
        float a = sh_alpha[idx >> 7];
        float4 v = reinterpret_cast<float4*>(out)[b4 + idx];
        v.x *= a; v.y *= a; v.z *= a; v.w *= a;
        reinterpret_cast<float4*>(out)[b4 + idx] = v;
    }
}

// ---------------------------------------------------------------------------
extern "C" void kernel_launch(void* const* d_in, const int* in_sizes, int n_in,
                              void* d_out, int out_size)
{
    const float* x   = (const float*)d_in[0];
    const float* W1  = (const float*)d_in[1];
    const float* b1  = (const float*)d_in[2];
    const float* W2  = (const float*)d_in[3];
    const float* b2  = (const float*)d_in[4];
    const float* Wv1 = (const float*)d_in[5];
    const float* Wv2 = (const float*)d_in[6];
    float* out = (float*)d_out;

    __nv_bfloat16* AFH  = 0; cudaGetSymbolAddress((void**)&AFH,  g_AFH);
    __nv_bfloat16* xlo  = 0; cudaGetSymbolAddress((void**)&xlo,  g_xlo);
    __nv_bfloat16* H1hi = 0; cudaGetSymbolAddress((void**)&H1hi, g_H1hi);
    __nv_bfloat16* H1lo = 0; cudaGetSymbolAddress((void**)&H1lo, g_H1lo);
    __nv_bfloat16* HXT  = 0; cudaGetSymbolAddress((void**)&HXT,  g_HXT);
    __nv_bfloat16* W1h = 0; cudaGetSymbolAddress((void**)&W1h, g_W1t_hi);
    __nv_bfloat16* W1l = 0; cudaGetSymbolAddress((void**)&W1l, g_W1t_lo);
    __nv_bfloat16* W2h = 0; cudaGetSymbolAddress((void**)&W2h, g_W2t_hi);
    __nv_bfloat16* W2l = 0; cudaGetSymbolAddress((void**)&W2l, g_W2t_lo);
    __nv_bfloat16* V1h = 0; cudaGetSymbolAddress((void**)&V1h, g_Wv1t_hi);
    __nv_bfloat16* V1l = 0; cudaGetSymbolAddress((void**)&V1l, g_Wv1t_lo);
    __nv_bfloat16* V2h = 0; cudaGetSymbolAddress((void**)&V2h, g_Wv2t_hi);

    __nv_bfloat16* xhi  = AFH;                            // rows [0, BATCH)
    __nv_bfloat16* FHhi = AFH + (size_t)BATCH * DIM;      // rows [BATCH, 2*BATCH)

    cudaFuncSetAttribute(tgemm<3,11>,         cudaFuncAttributeMaxDynamicSharedMemorySize, 98304);
    cudaFuncSetAttribute(tgemm<3,2|4|16|512>, cudaFuncAttributeMaxDynamicSharedMemorySize, 98304);
    cudaFuncSetAttribute(tgemm<1,17>,         cudaFuncAttributeMaxDynamicSharedMemorySize, 98304);
    cudaFuncSetAttribute(tgemm<1,256>,        cudaFuncAttributeMaxDynamicSharedMemorySize, 98304);

    // #1: fused prep (weight splits + x split + ||x||^2 + zero-init)
    prep_kernel<<<6552, 256>>>(x, W1, W2, Wv1, Wv2,
                               xhi, xlo, W1h, W1l, W2h, W2l, V1h, V1l, V2h);
    // #2: G1: H1(hi/lo) = tanh(x@W1 + b1)             [3-pass]
    tgemm<3, 1|2|8><<<dim3(HID / 128, BATCH / 128), 256, 98304>>>(
        HID, DIM, xhi, xlo, W1h, W1l, b1, 0, H1hi, H1lo);
    // #3: G2: out(=FH) + FHhi = H1@W2 + b2, sf reduce [3-pass]
    tgemm<3, 2|4|16|512><<<dim3(DIM / 128, BATCH / 128), 256, 98304>>>(
        DIM, HID, H1hi, H1lo, W2h, W2l, b2, out, FHhi, 0);
    // #4: G3+G5 fused: HXT = tanh([x;FH]@Wv1)         [1-pass BK64, M=16384]
    tgemm<1, 1|16><<<dim3(HV / 128, 2 * BATCH / 128), 256, 98304>>>(
        HV, DIM, AFH, 0, V1h, 0, 0, 0, HXT, 0);
    // #5: G4+G6 fused: rowsq(HXT @ Wv2) -> g_sq       [1-pass BK64, no store]
    tgemm<1, 256><<<dim3(VO / 128, 2 * BATCH / 128), 256, 98304>>>(
        VO, HV, HXT, 0, V2h, 0, 0, 0, 0, 0);
    // #6: newton (scalar residual check; out scaled in place only if needed)
    newton_kernel<<<BATCH / NG, 256>>>(Wv1, Wv2, out);
}